// round 3
// baseline (speedup 1.0000x reference)
#include <cuda_runtime.h>
#include <math.h>

// Problem constants
constexpr int BATCH = 2;
constexpr int SEQ   = 2048;
constexpr int EMB   = 1024;
constexpr int NH    = 16;
constexpr int HDIM  = 64;
constexpr int ROWS  = BATCH * SEQ;        // 4096

// Scratch: Q,K,V in [B,H,S,hd] layout (16 MB each)
__device__ float g_Q[BATCH * NH * SEQ * HDIM];
__device__ float g_K[BATCH * NH * SEQ * HDIM];
__device__ float g_V[BATCH * NH * SEQ * HDIM];

// ----------------------------------------------------------------------------
// Kernel 1: QKV projection GEMM.  out[b,h,s,d] = x[m,:] @ W[:,n] + bias[n]
// Tile: BM=128, BN=128, BK=16. 256 threads, 8x8 micro-tile per thread.
// grid = (EMB/128, ROWS/128, 3)  z selects (Wq,bq,Q)/(Wk,bk,K)/(Wv,bv,V)
// ----------------------------------------------------------------------------
__global__ __launch_bounds__(256) void qkv_gemm(
    const float* __restrict__ x,
    const float* __restrict__ Wq, const float* __restrict__ bq,
    const float* __restrict__ Wk, const float* __restrict__ bk,
    const float* __restrict__ Wv, const float* __restrict__ bv)
{
    const float* W;
    const float* bias;
    float* out;
    if (blockIdx.z == 0)      { W = Wq; bias = bq; out = g_Q; }
    else if (blockIdx.z == 1) { W = Wk; bias = bk; out = g_K; }
    else                      { W = Wv; bias = bv; out = g_V; }

    __shared__ float As[16][132];   // padded: store As[k][m], 2-way max conflict
    __shared__ float Bs[16][128];

    const int m0 = blockIdx.y * 128;
    const int n0 = blockIdx.x * 128;
    const int t  = threadIdx.x;
    const int ty = t >> 4;          // 0..15
    const int tx = t & 15;          // 0..15

    float acc[8][8];
    #pragma unroll
    for (int i = 0; i < 8; i++)
        #pragma unroll
        for (int j = 0; j < 8; j++) acc[i][j] = 0.f;

    for (int k0 = 0; k0 < EMB; k0 += 16) {
        // Load A tile: x[m0..m0+127][k0..k0+15] -> As[k][m]
        #pragma unroll
        for (int i = 0; i < 8; i++) {
            int idx = i * 256 + t;
            int m = idx >> 4;       // 0..127
            int k = idx & 15;       // 0..15
            As[k][m] = x[(size_t)(m0 + m) * EMB + (k0 + k)];
        }
        // Load B tile: W[k0..k0+15][n0..n0+127] -> Bs[k][n]  (coalesced)
        #pragma unroll
        for (int i = 0; i < 8; i++) {
            int idx = i * 256 + t;
            int n = idx & 127;
            int k = idx >> 7;
            Bs[k][n] = W[(size_t)(k0 + k) * EMB + (n0 + n)];
        }
        __syncthreads();

        #pragma unroll
        for (int k = 0; k < 16; k++) {
            float a[8], b[8];
            #pragma unroll
            for (int i = 0; i < 8; i++) a[i] = As[k][ty * 8 + i];
            #pragma unroll
            for (int j = 0; j < 8; j++) b[j] = Bs[k][tx * 8 + j];
            #pragma unroll
            for (int i = 0; i < 8; i++)
                #pragma unroll
                for (int j = 0; j < 8; j++)
                    acc[i][j] = fmaf(a[i], b[j], acc[i][j]);
        }
        __syncthreads();
    }

    // Epilogue: add bias, scatter into [B,H,S,hd] layout
    #pragma unroll
    for (int i = 0; i < 8; i++) {
        int m = m0 + ty * 8 + i;
        int b = m / SEQ;
        int s = m % SEQ;
        #pragma unroll
        for (int j = 0; j < 8; j++) {
            int n = n0 + tx * 8 + j;
            int h = n >> 6;
            int d = n & 63;
            out[(((size_t)(b * NH + h) * SEQ + s) * HDIM) + d] = acc[i][j] + bias[n];
        }
    }
}

// ----------------------------------------------------------------------------
// Kernel 2: flash attention, fp32.
// Block: 256 threads (16x16), Br=64 queries, Bc=64 keys, hd=64.
// Each thread: 4x4 micro-tiles for S and O. Online softmax; P through smem.
// grid = (SEQ/64, NH, BATCH).  Dynamic smem: 4 * 64 * 65 floats = 66,560 B.
// ----------------------------------------------------------------------------
__global__ __launch_bounds__(256) void attn(float* __restrict__ out)
{
    extern __shared__ float smem[];
    float (*Qs)[65] = (float(*)[65])(smem);
    float (*Ks)[65] = (float(*)[65])(smem + 64 * 65);
    float (*Vs)[65] = (float(*)[65])(smem + 2 * 64 * 65);
    float (*Ps)[65] = (float(*)[65])(smem + 3 * 64 * 65);

    const int b  = blockIdx.z;
    const int h  = blockIdx.y;
    const int q0 = blockIdx.x * 64;

    const float* Qp = g_Q + (size_t)(b * NH + h) * SEQ * HDIM;
    const float* Kp = g_K + (size_t)(b * NH + h) * SEQ * HDIM;
    const float* Vp = g_V + (size_t)(b * NH + h) * SEQ * HDIM;

    const int t  = threadIdx.x;
    const int ty = t >> 4;          // 0..15 -> rows ty*4..ty*4+3
    const int tx = t & 15;          // 0..15 -> cols tx*4..tx*4+3

    // Load Q tile, pre-scaled by 1/sqrt(hd)
    for (int i = t; i < 64 * 64; i += 256) {
        int r = i >> 6, d = i & 63;
        Qs[r][d] = Qp[(size_t)(q0 + r) * HDIM + d] * 0.125f;
    }
    __syncthreads();

    float m_i[4], l_i[4], O[4][4];
    #pragma unroll
    for (int i = 0; i < 4; i++) {
        m_i[i] = -1e30f;
        l_i[i] = 0.f;
        #pragma unroll
        for (int j = 0; j < 4; j++) O[i][j] = 0.f;
    }

    for (int kt = 0; kt < SEQ; kt += 64) {
        // Load K, V tiles
        for (int i = t; i < 64 * 64; i += 256) {
            int r = i >> 6, d = i & 63;
            Ks[r][d] = Kp[(size_t)(kt + r) * HDIM + d];
            Vs[r][d] = Vp[(size_t)(kt + r) * HDIM + d];
        }
        __syncthreads();

        // S = Q K^T  (thread owns rows ty*4+i, cols tx*4+j)
        float s[4][4];
        #pragma unroll
        for (int i = 0; i < 4; i++)
            #pragma unroll
            for (int j = 0; j < 4; j++) s[i][j] = 0.f;

        #pragma unroll 8
        for (int k = 0; k < 64; k++) {
            float qv[4], kv[4];
            #pragma unroll
            for (int i = 0; i < 4; i++) qv[i] = Qs[ty * 4 + i][k];
            #pragma unroll
            for (int j = 0; j < 4; j++) kv[j] = Ks[tx * 4 + j][k];
            #pragma unroll
            for (int i = 0; i < 4; i++)
                #pragma unroll
                for (int j = 0; j < 4; j++)
                    s[i][j] = fmaf(qv[i], kv[j], s[i][j]);
        }

        // Online softmax update (per row; reductions across the 16 tx lanes)
        #pragma unroll
        for (int i = 0; i < 4; i++) {
            float rmax = s[i][0];
            #pragma unroll
            for (int j = 1; j < 4; j++) rmax = fmaxf(rmax, s[i][j]);
            #pragma unroll
            for (int off = 8; off >= 1; off >>= 1)
                rmax = fmaxf(rmax, __shfl_xor_sync(0xffffffffu, rmax, off));

            float mnew  = fmaxf(m_i[i], rmax);
            float alpha = __expf(m_i[i] - mnew);
            m_i[i] = mnew;

            float rsum = 0.f;
            #pragma unroll
            for (int j = 0; j < 4; j++) {
                float p = __expf(s[i][j] - mnew);
                s[i][j] = p;
                rsum += p;
            }
            #pragma unroll
            for (int off = 8; off >= 1; off >>= 1)
                rsum += __shfl_xor_sync(0xffffffffu, rsum, off);

            l_i[i] = l_i[i] * alpha + rsum;
            #pragma unroll
            for (int j = 0; j < 4; j++) O[i][j] *= alpha;
        }

        // Stage P tile through smem for the PV product
        #pragma unroll
        for (int i = 0; i < 4; i++)
            #pragma unroll
            for (int j = 0; j < 4; j++)
                Ps[ty * 4 + i][tx * 4 + j] = s[i][j];
        __syncthreads();

        // O += P V   (thread owns rows ty*4+i, dims tx*4+j)
        #pragma unroll 8
        for (int c = 0; c < 64; c++) {
            float pv[4], vv[4];
            #pragma unroll
            for (int i = 0; i < 4; i++) pv[i] = Ps[ty * 4 + i][c];
            #pragma unroll
            for (int j = 0; j < 4; j++) vv[j] = Vs[c][tx * 4 + j];
            #pragma unroll
            for (int i = 0; i < 4; i++)
                #pragma unroll
                for (int j = 0; j < 4; j++)
                    O[i][j] = fmaf(pv[i], vv[j], O[i][j]);
        }
        __syncthreads();   // protect Ks/Vs/Ps before next tile's loads
    }

    // Epilogue: normalize and write out[b, s, h*64 + d]
    #pragma unroll
    for (int i = 0; i < 4; i++) {
        int r = q0 + ty * 4 + i;
        float inv = 1.f / l_i[i];
        #pragma unroll
        for (int j = 0; j < 4; j++) {
            int d = tx * 4 + j;
            out[((size_t)(b * SEQ + r) * EMB) + h * HDIM + d] = O[i][j] * inv;
        }
    }
}

// ----------------------------------------------------------------------------
extern "C" void kernel_launch(void* const* d_in, const int* in_sizes, int n_in,
                              void* d_out, int out_size)
{
    const float* x  = (const float*)d_in[0];
    const float* Wq = (const float*)d_in[1];
    const float* bq = (const float*)d_in[2];
    const float* Wk = (const float*)d_in[3];
    const float* bk = (const float*)d_in[4];
    const float* Wv = (const float*)d_in[5];
    const float* bv = (const float*)d_in[6];
    float* out = (float*)d_out;

    // QKV projections
    dim3 g1(EMB / 128, ROWS / 128, 3);
    qkv_gemm<<<g1, 256>>>(x, Wq, bq, Wk, bk, Wv, bv);

    // Attention
    size_t smem_bytes = 4 * 64 * 65 * sizeof(float);   // 66,560 B
    static bool attr_set = false;
    if (!attr_set) {
        cudaFuncSetAttribute(attn, cudaFuncAttributeMaxDynamicSharedMemorySize,
                             (int)smem_bytes);
        attr_set = true;
    }
    dim3 g2(SEQ / 64, NH, BATCH);
    attn<<<g2, 256, smem_bytes>>>(out);
}

// round 4
// speedup vs baseline: 3.6487x; 3.6487x over previous
#include <cuda_runtime.h>
#include <math.h>

// Problem constants
constexpr int BATCH = 2;
constexpr int SEQ   = 2048;
constexpr int EMB   = 1024;
constexpr int NH    = 16;
constexpr int HDIM  = 64;
constexpr int ROWS  = BATCH * SEQ;        // 4096

// Scratch. Q,K in [B,H,S,hd]. V stored TRANSPOSED: [B,H,hd,S] so the
// attention PV mma's B operand (needs k=c contiguous) is natural.
__device__ float g_Q[BATCH * NH * SEQ * HDIM];
__device__ float g_K[BATCH * NH * SEQ * HDIM];
__device__ float g_V[BATCH * NH * SEQ * HDIM];

// ---- tf32 helpers -----------------------------------------------------------
__device__ __forceinline__ unsigned f2tf(float f) {
    unsigned u;
    asm("cvt.rna.tf32.f32 %0, %1;" : "=r"(u) : "f"(f));
    return u;
}

// D = A(16x8,row) * B(8x8,col) + D, tf32 in / fp32 accum.
// a0:(r=g, k=t) a1:(r=g+8,k=t) a2:(r=g,k=t+4) a3:(r=g+8,k=t+4)
// b0:(k=t, n=g) b1:(k=t+4,n=g)
// c0:(r=g, n=2t) c1:(r=g,n=2t+1) c2:(r=g+8,n=2t) c3:(r=g+8,n=2t+1)
//   where g = lane>>2, t = lane&3
__device__ __forceinline__ void mma8(float c[4], const unsigned a[4], const unsigned b[2]) {
    asm volatile(
        "mma.sync.aligned.m16n8k8.row.col.f32.tf32.tf32.f32 "
        "{%0,%1,%2,%3}, {%4,%5,%6,%7}, {%8,%9}, {%0,%1,%2,%3};"
        : "+f"(c[0]), "+f"(c[1]), "+f"(c[2]), "+f"(c[3])
        : "r"(a[0]), "r"(a[1]), "r"(a[2]), "r"(a[3]), "r"(b[0]), "r"(b[1]));
}

// ----------------------------------------------------------------------------
// Kernel 1: QKV projection, tf32 tensor cores.
// CTA tile 128x128, BK=32. 256 thr = 8 warps (2m x 4n), warp tile 64x32.
// grid = (EMB/128, ROWS/128, 3)
// As[m][k] stride 36 (36%32=4 -> frag LDS bank == lane, conflict-free)
// Bs[k][n] stride 136 (136%32=8 -> frag LDS conflict-free)
// ----------------------------------------------------------------------------
__global__ __launch_bounds__(256) void qkv_gemm(
    const float* __restrict__ x,
    const float* __restrict__ Wq, const float* __restrict__ bq,
    const float* __restrict__ Wk, const float* __restrict__ bk,
    const float* __restrict__ Wv, const float* __restrict__ bv)
{
    const float* W;
    const float* bias;
    float* out;
    bool isv = false;
    if (blockIdx.z == 0)      { W = Wq; bias = bq; out = g_Q; }
    else if (blockIdx.z == 1) { W = Wk; bias = bk; out = g_K; }
    else                      { W = Wv; bias = bv; out = g_V; isv = true; }

    __shared__ unsigned As[128][36];   // 18,432 B
    __shared__ unsigned Bs[32][136];   // 17,408 B

    const int m0   = blockIdx.y * 128;
    const int n0   = blockIdx.x * 128;
    const int t    = threadIdx.x;
    const int lane = t & 31;
    const int wid  = t >> 5;
    const int wm   = wid >> 2;          // 0..1 -> m offset 64
    const int wn   = wid & 3;           // 0..3 -> n offset 32
    const int g    = lane >> 2;         // group id 0..7
    const int tg   = lane & 3;          // thread-in-group 0..3

    float acc[4][4][4];
    #pragma unroll
    for (int im = 0; im < 4; im++)
        #pragma unroll
        for (int in_ = 0; in_ < 4; in_++)
            #pragma unroll
            for (int r = 0; r < 4; r++) acc[im][in_][r] = 0.f;

    for (int k0 = 0; k0 < EMB; k0 += 32) {
        // A tile: x[m0+m][k0+k], m<128, k<32. float4 along k, conflict-free STS.
        #pragma unroll
        for (int it = 0; it < 4; it++) {
            int id = it * 256 + t;
            int m  = id >> 3;
            int kc = id & 7;
            float4 v = *(const float4*)&x[(size_t)(m0 + m) * EMB + k0 + kc * 4];
            *(uint4*)&As[m][kc * 4] =
                make_uint4(f2tf(v.x), f2tf(v.y), f2tf(v.z), f2tf(v.w));
        }
        // B tile: W[k0+k][n0+n], k<32, n<128. float4 along n.
        #pragma unroll
        for (int it = 0; it < 4; it++) {
            int k  = it * 8 + wid;
            int n4 = lane;
            float4 v = *(const float4*)&W[(size_t)(k0 + k) * EMB + n0 + n4 * 4];
            *(uint4*)&Bs[k][n4 * 4] =
                make_uint4(f2tf(v.x), f2tf(v.y), f2tf(v.z), f2tf(v.w));
        }
        __syncthreads();

        #pragma unroll
        for (int ks = 0; ks < 4; ks++) {
            const int k8 = ks * 8;
            unsigned a[4][4], b[4][2];
            #pragma unroll
            for (int im = 0; im < 4; im++) {
                int row = wm * 64 + im * 16 + g;
                a[im][0] = As[row][k8 + tg];
                a[im][1] = As[row + 8][k8 + tg];
                a[im][2] = As[row][k8 + 4 + tg];
                a[im][3] = As[row + 8][k8 + 4 + tg];
            }
            #pragma unroll
            for (int in_ = 0; in_ < 4; in_++) {
                int col = wn * 32 + in_ * 8 + g;
                b[in_][0] = Bs[k8 + tg][col];
                b[in_][1] = Bs[k8 + 4 + tg][col];
            }
            #pragma unroll
            for (int im = 0; im < 4; im++)
                #pragma unroll
                for (int in_ = 0; in_ < 4; in_++)
                    mma8(acc[im][in_], a[im], b[in_]);
        }
        __syncthreads();
    }

    // Epilogue: add bias; scatter Q,K -> [b,h,s,d]; V -> [b,h,d,s]
    #pragma unroll
    for (int im = 0; im < 4; im++) {
        int rbase = m0 + wm * 64 + im * 16 + g;
        #pragma unroll
        for (int in_ = 0; in_ < 4; in_++) {
            int col = n0 + wn * 32 + in_ * 8 + 2 * tg;
            float b0 = bias[col], b1 = bias[col + 1];
            int h = col >> 6, d = col & 63;
            #pragma unroll
            for (int half = 0; half < 2; half++) {
                int r  = rbase + half * 8;
                int bb = r >> 11;            // / SEQ
                int s  = r & 2047;           // % SEQ
                float v0 = acc[im][in_][half * 2 + 0] + b0;
                float v1 = acc[im][in_][half * 2 + 1] + b1;
                if (!isv) {
                    size_t base = (((size_t)(bb * NH + h) * SEQ + s) * HDIM) + d;
                    *(float2*)&out[base] = make_float2(v0, v1);
                } else {
                    size_t base = ((size_t)(bb * NH + h) * HDIM + d) * SEQ + s;
                    out[base]       = v0;
                    out[base + SEQ] = v1;
                }
            }
        }
    }
}

// ----------------------------------------------------------------------------
// Kernel 2: flash attention, tf32 tensor cores.
// Block = 128 thr (4 warps). Br=64 (16 rows/warp), Bc=64, hd=64.
// S = Q K^T : A = Qs[q][d] (k-contig), B = Ks[c][d] (k-contig, "col") - natural!
// PV       : A = Ps[q][c],            B = Vt[d][c] (from transposed g_V)
// All smem stride 68 (68%32=4 -> every fragment LDS is conflict-free).
// Dynamic smem: 4 * 64 * 68 * 4 = 69,632 B.
// ----------------------------------------------------------------------------
__global__ __launch_bounds__(128) void attn(float* __restrict__ out)
{
    extern __shared__ unsigned smem[];
    unsigned (*Qs)[68] = (unsigned(*)[68])(smem);
    unsigned (*Ks)[68] = (unsigned(*)[68])(smem + 64 * 68);
    unsigned (*Vt)[68] = (unsigned(*)[68])(smem + 2 * 64 * 68);
    unsigned (*Ps)[68] = (unsigned(*)[68])(smem + 3 * 64 * 68);

    const int b  = blockIdx.z;
    const int h  = blockIdx.y;
    const int q0 = blockIdx.x * 64;
    const int bh = b * NH + h;

    const float* Qp = g_Q + (size_t)bh * SEQ * HDIM;
    const float* Kp = g_K + (size_t)bh * SEQ * HDIM;
    const float* Vp = g_V + (size_t)bh * HDIM * SEQ;   // [d][s]

    const int t    = threadIdx.x;
    const int lane = t & 31;
    const int wid  = t >> 5;
    const int g    = lane >> 2;
    const int tg   = lane & 3;
    const int r0   = wid * 16 + g;      // this thread's first S/O row

    // Load Q tile (pre-scaled by 1/sqrt(hd)=0.125), tf32-converted.
    #pragma unroll
    for (int it = 0; it < 8; it++) {
        int id = it * 128 + t;
        int r = id >> 4, d4 = id & 15;
        float4 v = *(const float4*)&Qp[(size_t)(q0 + r) * HDIM + d4 * 4];
        *(uint4*)&Qs[r][d4 * 4] = make_uint4(
            f2tf(v.x * 0.125f), f2tf(v.y * 0.125f),
            f2tf(v.z * 0.125f), f2tf(v.w * 0.125f));
    }

    float o[8][4];
    #pragma unroll
    for (int nt = 0; nt < 8; nt++)
        #pragma unroll
        for (int r = 0; r < 4; r++) o[nt][r] = 0.f;
    float m0v = -1e30f, m1v = -1e30f, l0 = 0.f, l1 = 0.f;

    for (int kt = 0; kt < SEQ; kt += 64) {
        // K tile [c][d] and V^T tile [d][c]
        #pragma unroll
        for (int it = 0; it < 8; it++) {
            int id = it * 128 + t;
            int r = id >> 4, c4 = id & 15;
            float4 kv = *(const float4*)&Kp[(size_t)(kt + r) * HDIM + c4 * 4];
            *(uint4*)&Ks[r][c4 * 4] =
                make_uint4(f2tf(kv.x), f2tf(kv.y), f2tf(kv.z), f2tf(kv.w));
            float4 vv = *(const float4*)&Vp[(size_t)r * SEQ + kt + c4 * 4];
            *(uint4*)&Vt[r][c4 * 4] =
                make_uint4(f2tf(vv.x), f2tf(vv.y), f2tf(vv.z), f2tf(vv.w));
        }
        __syncthreads();

        // S = Q K^T fragments: rows r0, r0+8; cols nt*8 + 2*tg (+1)
        float s[8][4];
        #pragma unroll
        for (int nt = 0; nt < 8; nt++)
            #pragma unroll
            for (int r = 0; r < 4; r++) s[nt][r] = 0.f;

        #pragma unroll
        for (int ks = 0; ks < 8; ks++) {
            const int k8 = ks * 8;
            unsigned a[4];
            a[0] = Qs[r0][k8 + tg];
            a[1] = Qs[r0 + 8][k8 + tg];
            a[2] = Qs[r0][k8 + 4 + tg];
            a[3] = Qs[r0 + 8][k8 + 4 + tg];
            #pragma unroll
            for (int nt = 0; nt < 8; nt++) {
                unsigned bb[2];
                bb[0] = Ks[nt * 8 + g][k8 + tg];
                bb[1] = Ks[nt * 8 + g][k8 + 4 + tg];
                mma8(s[nt], a, bb);
            }
        }

        // Online softmax. Rows live in quads (lanes sharing lane>>2).
        float mx0 = -1e30f, mx1 = -1e30f;
        #pragma unroll
        for (int nt = 0; nt < 8; nt++) {
            mx0 = fmaxf(mx0, fmaxf(s[nt][0], s[nt][1]));
            mx1 = fmaxf(mx1, fmaxf(s[nt][2], s[nt][3]));
        }
        mx0 = fmaxf(mx0, __shfl_xor_sync(0xffffffffu, mx0, 1));
        mx0 = fmaxf(mx0, __shfl_xor_sync(0xffffffffu, mx0, 2));
        mx1 = fmaxf(mx1, __shfl_xor_sync(0xffffffffu, mx1, 1));
        mx1 = fmaxf(mx1, __shfl_xor_sync(0xffffffffu, mx1, 2));

        float mn0 = fmaxf(m0v, mx0), mn1 = fmaxf(m1v, mx1);
        float al0 = __expf(m0v - mn0), al1 = __expf(m1v - mn1);
        m0v = mn0; m1v = mn1;

        float sum0 = 0.f, sum1 = 0.f;
        const int cb = 2 * tg;
        #pragma unroll
        for (int nt = 0; nt < 8; nt++) {
            float p0 = __expf(s[nt][0] - mn0);
            float p1 = __expf(s[nt][1] - mn0);
            float p2 = __expf(s[nt][2] - mn1);
            float p3 = __expf(s[nt][3] - mn1);
            sum0 += p0 + p1;
            sum1 += p2 + p3;
            *(uint2*)&Ps[r0][nt * 8 + cb]     = make_uint2(f2tf(p0), f2tf(p1));
            *(uint2*)&Ps[r0 + 8][nt * 8 + cb] = make_uint2(f2tf(p2), f2tf(p3));
            o[nt][0] *= al0; o[nt][1] *= al0;
            o[nt][2] *= al1; o[nt][3] *= al1;
        }
        sum0 += __shfl_xor_sync(0xffffffffu, sum0, 1);
        sum0 += __shfl_xor_sync(0xffffffffu, sum0, 2);
        sum1 += __shfl_xor_sync(0xffffffffu, sum1, 1);
        sum1 += __shfl_xor_sync(0xffffffffu, sum1, 2);
        l0 = l0 * al0 + sum0;
        l1 = l1 * al1 + sum1;

        __syncwarp();   // Ps rows are warp-private; exchange within warp only

        // O += P V : A = Ps (k=c contig), B = Vt[d][c] (k=c contig)
        #pragma unroll
        for (int ks = 0; ks < 8; ks++) {
            const int k8 = ks * 8;
            unsigned a[4];
            a[0] = Ps[r0][k8 + tg];
            a[1] = Ps[r0 + 8][k8 + tg];
            a[2] = Ps[r0][k8 + 4 + tg];
            a[3] = Ps[r0 + 8][k8 + 4 + tg];
            #pragma unroll
            for (int nt = 0; nt < 8; nt++) {
                unsigned bb[2];
                bb[0] = Vt[nt * 8 + g][k8 + tg];
                bb[1] = Vt[nt * 8 + g][k8 + 4 + tg];
                mma8(o[nt], a, bb);
            }
        }
        __syncthreads();   // protect Ks/Vt before next tile's loads
    }

    // Epilogue: normalize, write out[b, s, h*64 + d]
    float inv0 = 1.f / l0, inv1 = 1.f / l1;
    #pragma unroll
    for (int nt = 0; nt < 8; nt++) {
        int d = h * HDIM + nt * 8 + 2 * tg;
        size_t base0 = ((size_t)(b * SEQ + q0 + r0)) * EMB + d;
        size_t base1 = ((size_t)(b * SEQ + q0 + r0 + 8)) * EMB + d;
        *(float2*)&out[base0] = make_float2(o[nt][0] * inv0, o[nt][1] * inv0);
        *(float2*)&out[base1] = make_float2(o[nt][2] * inv1, o[nt][3] * inv1);
    }
}

// ----------------------------------------------------------------------------
extern "C" void kernel_launch(void* const* d_in, const int* in_sizes, int n_in,
                              void* d_out, int out_size)
{
    const float* x  = (const float*)d_in[0];
    const float* Wq = (const float*)d_in[1];
    const float* bq = (const float*)d_in[2];
    const float* Wk = (const float*)d_in[3];
    const float* bk = (const float*)d_in[4];
    const float* Wv = (const float*)d_in[5];
    const float* bv = (const float*)d_in[6];
    float* out = (float*)d_out;

    dim3 g1(EMB / 128, ROWS / 128, 3);
    qkv_gemm<<<g1, 256>>>(x, Wq, bq, Wk, bk, Wv, bv);

    size_t smem_bytes = 4 * 64 * 68 * sizeof(unsigned);   // 69,632 B
    static bool attr_set = false;
    if (!attr_set) {
        cudaFuncSetAttribute(attn, cudaFuncAttributeMaxDynamicSharedMemorySize,
                             (int)smem_bytes);
        attr_set = true;
    }
    dim3 g2(SEQ / 64, NH, BATCH);
    attn<<<g2, 128, smem_bytes>>>(out);
}

// round 5
// speedup vs baseline: 3.6503x; 1.0004x over previous
#include <cuda_runtime.h>
#include <math.h>

// Problem constants
constexpr int BATCH = 2;
constexpr int SEQ   = 2048;
constexpr int EMB   = 1024;
constexpr int NH    = 16;
constexpr int HDIM  = 64;
constexpr int ROWS  = BATCH * SEQ;        // 4096

// Scratch. Q,K in [B,H,S,hd]. V stored TRANSPOSED: [B,H,hd,S] so the
// attention PV mma's B operand (needs k=c contiguous) is natural.
__device__ float g_Q[BATCH * NH * SEQ * HDIM];
__device__ float g_K[BATCH * NH * SEQ * HDIM];
__device__ float g_V[BATCH * NH * SEQ * HDIM];

// ---- tf32 helpers -----------------------------------------------------------
__device__ __forceinline__ unsigned f2tf(float f) {
    unsigned u;
    asm("cvt.rna.tf32.f32 %0, %1;" : "=r"(u) : "f"(f));
    return u;
}

// D = A(16x8,row) * B(8x8,col) + D, tf32 in / fp32 accum.
// a0:(r=g, k=t) a1:(r=g+8,k=t) a2:(r=g,k=t+4) a3:(r=g+8,k=t+4)
// b0:(k=t, n=g) b1:(k=t+4,n=g)
// c0:(r=g, n=2t) c1:(r=g,n=2t+1) c2:(r=g+8,n=2t) c3:(r=g+8,n=2t+1)
//   where g = lane>>2, t = lane&3
__device__ __forceinline__ void mma8(float c[4], const unsigned a[4], const unsigned b[2]) {
    asm volatile(
        "mma.sync.aligned.m16n8k8.row.col.f32.tf32.tf32.f32 "
        "{%0,%1,%2,%3}, {%4,%5,%6,%7}, {%8,%9}, {%0,%1,%2,%3};"
        : "+f"(c[0]), "+f"(c[1]), "+f"(c[2]), "+f"(c[3])
        : "r"(a[0]), "r"(a[1]), "r"(a[2]), "r"(a[3]), "r"(b[0]), "r"(b[1]));
}

// ----------------------------------------------------------------------------
// Kernel 1: QKV projection, tf32 tensor cores.
// CTA tile 128x128, BK=32. 256 thr = 8 warps (2m x 4n), warp tile 64x32.
// grid = (EMB/128, ROWS/128, 3)
// As[m][k] stride 36 (36%32=4 -> frag LDS bank == lane, conflict-free)
// Bs[k][n] stride 136 (136%32=8 -> frag LDS conflict-free)
// ----------------------------------------------------------------------------
__global__ __launch_bounds__(256) void qkv_gemm(
    const float* __restrict__ x,
    const float* __restrict__ Wq, const float* __restrict__ bq,
    const float* __restrict__ Wk, const float* __restrict__ bk,
    const float* __restrict__ Wv, const float* __restrict__ bv)
{
    const float* W;
    const float* bias;
    float* out;
    bool isv = false;
    if (blockIdx.z == 0)      { W = Wq; bias = bq; out = g_Q; }
    else if (blockIdx.z == 1) { W = Wk; bias = bk; out = g_K; }
    else                      { W = Wv; bias = bv; out = g_V; isv = true; }

    __shared__ unsigned As[128][36];   // 18,432 B
    __shared__ unsigned Bs[32][136];   // 17,408 B

    const int m0   = blockIdx.y * 128;
    const int n0   = blockIdx.x * 128;
    const int t    = threadIdx.x;
    const int lane = t & 31;
    const int wid  = t >> 5;
    const int wm   = wid >> 2;          // 0..1 -> m offset 64
    const int wn   = wid & 3;           // 0..3 -> n offset 32
    const int g    = lane >> 2;         // group id 0..7
    const int tg   = lane & 3;          // thread-in-group 0..3

    float acc[4][4][4];
    #pragma unroll
    for (int im = 0; im < 4; im++)
        #pragma unroll
        for (int in_ = 0; in_ < 4; in_++)
            #pragma unroll
            for (int r = 0; r < 4; r++) acc[im][in_][r] = 0.f;

    for (int k0 = 0; k0 < EMB; k0 += 32) {
        // A tile: x[m0+m][k0+k], m<128, k<32. float4 along k, conflict-free STS.
        #pragma unroll
        for (int it = 0; it < 4; it++) {
            int id = it * 256 + t;
            int m  = id >> 3;
            int kc = id & 7;
            float4 v = *(const float4*)&x[(size_t)(m0 + m) * EMB + k0 + kc * 4];
            *(uint4*)&As[m][kc * 4] =
                make_uint4(f2tf(v.x), f2tf(v.y), f2tf(v.z), f2tf(v.w));
        }
        // B tile: W[k0+k][n0+n], k<32, n<128. float4 along n.
        #pragma unroll
        for (int it = 0; it < 4; it++) {
            int k  = it * 8 + wid;
            int n4 = lane;
            float4 v = *(const float4*)&W[(size_t)(k0 + k) * EMB + n0 + n4 * 4];
            *(uint4*)&Bs[k][n4 * 4] =
                make_uint4(f2tf(v.x), f2tf(v.y), f2tf(v.z), f2tf(v.w));
        }
        __syncthreads();

        #pragma unroll
        for (int ks = 0; ks < 4; ks++) {
            const int k8 = ks * 8;
            unsigned a[4][4], b[4][2];
            #pragma unroll
            for (int im = 0; im < 4; im++) {
                int row = wm * 64 + im * 16 + g;
                a[im][0] = As[row][k8 + tg];
                a[im][1] = As[row + 8][k8 + tg];
                a[im][2] = As[row][k8 + 4 + tg];
                a[im][3] = As[row + 8][k8 + 4 + tg];
            }
            #pragma unroll
            for (int in_ = 0; in_ < 4; in_++) {
                int col = wn * 32 + in_ * 8 + g;
                b[in_][0] = Bs[k8 + tg][col];
                b[in_][1] = Bs[k8 + 4 + tg][col];
            }
            #pragma unroll
            for (int im = 0; im < 4; im++)
                #pragma unroll
                for (int in_ = 0; in_ < 4; in_++)
                    mma8(acc[im][in_], a[im], b[in_]);
        }
        __syncthreads();
    }

    // Epilogue: add bias; scatter Q,K -> [b,h,s,d]; V -> [b,h,d,s]
    #pragma unroll
    for (int im = 0; im < 4; im++) {
        int rbase = m0 + wm * 64 + im * 16 + g;
        #pragma unroll
        for (int in_ = 0; in_ < 4; in_++) {
            int col = n0 + wn * 32 + in_ * 8 + 2 * tg;
            float b0 = bias[col], b1 = bias[col + 1];
            int h = col >> 6, d = col & 63;
            #pragma unroll
            for (int half = 0; half < 2; half++) {
                int r  = rbase + half * 8;
                int bb = r >> 11;            // / SEQ
                int s  = r & 2047;           // % SEQ
                float v0 = acc[im][in_][half * 2 + 0] + b0;
                float v1 = acc[im][in_][half * 2 + 1] + b1;
                if (!isv) {
                    size_t base = (((size_t)(bb * NH + h) * SEQ + s) * HDIM) + d;
                    *(float2*)&out[base] = make_float2(v0, v1);
                } else {
                    size_t base = ((size_t)(bb * NH + h) * HDIM + d) * SEQ + s;
                    out[base]       = v0;
                    out[base + SEQ] = v1;
                }
            }
        }
    }
}

// ----------------------------------------------------------------------------
// Kernel 2: flash attention, tf32 tensor cores.
// Block = 128 thr (4 warps). Br=64 (16 rows/warp), Bc=64, hd=64.
// S = Q K^T : A = Qs[q][d] (k-contig), B = Ks[c][d] (k-contig, "col") - natural!
// PV       : A = Ps[q][c],            B = Vt[d][c] (from transposed g_V)
// All smem stride 68 (68%32=4 -> every fragment LDS is conflict-free).
// Dynamic smem: 4 * 64 * 68 * 4 = 69,632 B.
// ----------------------------------------------------------------------------
__global__ __launch_bounds__(128) void attn(float* __restrict__ out)
{
    extern __shared__ unsigned smem[];
    unsigned (*Qs)[68] = (unsigned(*)[68])(smem);
    unsigned (*Ks)[68] = (unsigned(*)[68])(smem + 64 * 68);
    unsigned (*Vt)[68] = (unsigned(*)[68])(smem + 2 * 64 * 68);
    unsigned (*Ps)[68] = (unsigned(*)[68])(smem + 3 * 64 * 68);

    const int b  = blockIdx.z;
    const int h  = blockIdx.y;
    const int q0 = blockIdx.x * 64;
    const int bh = b * NH + h;

    const float* Qp = g_Q + (size_t)bh * SEQ * HDIM;
    const float* Kp = g_K + (size_t)bh * SEQ * HDIM;
    const float* Vp = g_V + (size_t)bh * HDIM * SEQ;   // [d][s]

    const int t    = threadIdx.x;
    const int lane = t & 31;
    const int wid  = t >> 5;
    const int g    = lane >> 2;
    const int tg   = lane & 3;
    const int r0   = wid * 16 + g;      // this thread's first S/O row

    // Load Q tile (pre-scaled by 1/sqrt(hd)=0.125), tf32-converted.
    #pragma unroll
    for (int it = 0; it < 8; it++) {
        int id = it * 128 + t;
        int r = id >> 4, d4 = id & 15;
        float4 v = *(const float4*)&Qp[(size_t)(q0 + r) * HDIM + d4 * 4];
        *(uint4*)&Qs[r][d4 * 4] = make_uint4(
            f2tf(v.x * 0.125f), f2tf(v.y * 0.125f),
            f2tf(v.z * 0.125f), f2tf(v.w * 0.125f));
    }

    float o[8][4];
    #pragma unroll
    for (int nt = 0; nt < 8; nt++)
        #pragma unroll
        for (int r = 0; r < 4; r++) o[nt][r] = 0.f;
    float m0v = -1e30f, m1v = -1e30f, l0 = 0.f, l1 = 0.f;

    for (int kt = 0; kt < SEQ; kt += 64) {
        // K tile [c][d] and V^T tile [d][c]
        #pragma unroll
        for (int it = 0; it < 8; it++) {
            int id = it * 128 + t;
            int r = id >> 4, c4 = id & 15;
            float4 kv = *(const float4*)&Kp[(size_t)(kt + r) * HDIM + c4 * 4];
            *(uint4*)&Ks[r][c4 * 4] =
                make_uint4(f2tf(kv.x), f2tf(kv.y), f2tf(kv.z), f2tf(kv.w));
            float4 vv = *(const float4*)&Vp[(size_t)r * SEQ + kt + c4 * 4];
            *(uint4*)&Vt[r][c4 * 4] =
                make_uint4(f2tf(vv.x), f2tf(vv.y), f2tf(vv.z), f2tf(vv.w));
        }
        __syncthreads();

        // S = Q K^T fragments: rows r0, r0+8; cols nt*8 + 2*tg (+1)
        float s[8][4];
        #pragma unroll
        for (int nt = 0; nt < 8; nt++)
            #pragma unroll
            for (int r = 0; r < 4; r++) s[nt][r] = 0.f;

        #pragma unroll
        for (int ks = 0; ks < 8; ks++) {
            const int k8 = ks * 8;
            unsigned a[4];
            a[0] = Qs[r0][k8 + tg];
            a[1] = Qs[r0 + 8][k8 + tg];
            a[2] = Qs[r0][k8 + 4 + tg];
            a[3] = Qs[r0 + 8][k8 + 4 + tg];
            #pragma unroll
            for (int nt = 0; nt < 8; nt++) {
                unsigned bb[2];
                bb[0] = Ks[nt * 8 + g][k8 + tg];
                bb[1] = Ks[nt * 8 + g][k8 + 4 + tg];
                mma8(s[nt], a, bb);
            }
        }

        // Online softmax. Rows live in quads (lanes sharing lane>>2).
        float mx0 = -1e30f, mx1 = -1e30f;
        #pragma unroll
        for (int nt = 0; nt < 8; nt++) {
            mx0 = fmaxf(mx0, fmaxf(s[nt][0], s[nt][1]));
            mx1 = fmaxf(mx1, fmaxf(s[nt][2], s[nt][3]));
        }
        mx0 = fmaxf(mx0, __shfl_xor_sync(0xffffffffu, mx0, 1));
        mx0 = fmaxf(mx0, __shfl_xor_sync(0xffffffffu, mx0, 2));
        mx1 = fmaxf(mx1, __shfl_xor_sync(0xffffffffu, mx1, 1));
        mx1 = fmaxf(mx1, __shfl_xor_sync(0xffffffffu, mx1, 2));

        float mn0 = fmaxf(m0v, mx0), mn1 = fmaxf(m1v, mx1);
        float al0 = __expf(m0v - mn0), al1 = __expf(m1v - mn1);
        m0v = mn0; m1v = mn1;

        float sum0 = 0.f, sum1 = 0.f;
        const int cb = 2 * tg;
        #pragma unroll
        for (int nt = 0; nt < 8; nt++) {
            float p0 = __expf(s[nt][0] - mn0);
            float p1 = __expf(s[nt][1] - mn0);
            float p2 = __expf(s[nt][2] - mn1);
            float p3 = __expf(s[nt][3] - mn1);
            sum0 += p0 + p1;
            sum1 += p2 + p3;
            *(uint2*)&Ps[r0][nt * 8 + cb]     = make_uint2(f2tf(p0), f2tf(p1));
            *(uint2*)&Ps[r0 + 8][nt * 8 + cb] = make_uint2(f2tf(p2), f2tf(p3));
            o[nt][0] *= al0; o[nt][1] *= al0;
            o[nt][2] *= al1; o[nt][3] *= al1;
        }
        sum0 += __shfl_xor_sync(0xffffffffu, sum0, 1);
        sum0 += __shfl_xor_sync(0xffffffffu, sum0, 2);
        sum1 += __shfl_xor_sync(0xffffffffu, sum1, 1);
        sum1 += __shfl_xor_sync(0xffffffffu, sum1, 2);
        l0 = l0 * al0 + sum0;
        l1 = l1 * al1 + sum1;

        __syncwarp();   // Ps rows are warp-private; exchange within warp only

        // O += P V : A = Ps (k=c contig), B = Vt[d][c] (k=c contig)
        #pragma unroll
        for (int ks = 0; ks < 8; ks++) {
            const int k8 = ks * 8;
            unsigned a[4];
            a[0] = Ps[r0][k8 + tg];
            a[1] = Ps[r0 + 8][k8 + tg];
            a[2] = Ps[r0][k8 + 4 + tg];
            a[3] = Ps[r0 + 8][k8 + 4 + tg];
            #pragma unroll
            for (int nt = 0; nt < 8; nt++) {
                unsigned bb[2];
                bb[0] = Vt[nt * 8 + g][k8 + tg];
                bb[1] = Vt[nt * 8 + g][k8 + 4 + tg];
                mma8(o[nt], a, bb);
            }
        }
        __syncthreads();   // protect Ks/Vt before next tile's loads
    }

    // Epilogue: normalize, write out[b, s, h*64 + d]
    float inv0 = 1.f / l0, inv1 = 1.f / l1;
    #pragma unroll
    for (int nt = 0; nt < 8; nt++) {
        int d = h * HDIM + nt * 8 + 2 * tg;
        size_t base0 = ((size_t)(b * SEQ + q0 + r0)) * EMB + d;
        size_t base1 = ((size_t)(b * SEQ + q0 + r0 + 8)) * EMB + d;
        *(float2*)&out[base0] = make_float2(o[nt][0] * inv0, o[nt][1] * inv0);
        *(float2*)&out[base1] = make_float2(o[nt][2] * inv1, o[nt][3] * inv1);
    }
}

// ----------------------------------------------------------------------------
extern "C" void kernel_launch(void* const* d_in, const int* in_sizes, int n_in,
                              void* d_out, int out_size)
{
    const float* x  = (const float*)d_in[0];
    const float* Wq = (const float*)d_in[1];
    const float* bq = (const float*)d_in[2];
    const float* Wk = (const float*)d_in[3];
    const float* bk = (const float*)d_in[4];
    const float* Wv = (const float*)d_in[5];
    const float* bv = (const float*)d_in[6];
    float* out = (float*)d_out;

    dim3 g1(EMB / 128, ROWS / 128, 3);
    qkv_gemm<<<g1, 256>>>(x, Wq, bq, Wk, bk, Wv, bv);

    size_t smem_bytes = 4 * 64 * 68 * sizeof(unsigned);   // 69,632 B
    static bool attr_set = false;
    if (!attr_set) {
        cudaFuncSetAttribute(attn, cudaFuncAttributeMaxDynamicSharedMemorySize,
                             (int)smem_bytes);
        attr_set = true;
    }
    dim3 g2(SEQ / 64, NH, BATCH);
    attn<<<g2, 128, smem_bytes>>>(out);
}